// round 3
// baseline (speedup 1.0000x reference)
#include <cuda_runtime.h>
#include <cuda_bf16.h>
#include <cstdint>
#include <math.h>

// Problem constants
#define Bdim 4
#define Ldim 8192
#define Ddim 512
#define Mdim (Bdim * Ldim)   // 32768
#define Ntot (2 * Ddim)      // 1024 (gate preact cols 0..511, cand 512..1023)
#define Kdim 512

// GEMM tiling
#define BM 128
#define BN 128
#define BK 32
#define BKP 36   // padded smem stride (floats): 4-bank shift/row, 16B aligned

// Scan config
#define CHUNK 256
#define NCHUNK (Ldim / CHUNK)        // 32 (== warp size, handy)
#define NCHAN (Bdim * Ddim)          // 2048 channels

// ---------------- scratch (no cudaMalloc allowed) ----------------
__device__ float g_gate[(size_t)Mdim * Ddim];   // sigmoid(x Wg^T + bg), [B,L,D]
__device__ float c_cand[(size_t)Mdim * Ddim];   // tanh(x Wc^T + bc),   [B,L,D]
__device__ float2 chunkAB[NCHAN * NCHUNK];      // per-chunk composed (A, B)
__device__ float  chunkH[NCHAN * NCHUNK];       // h before each chunk

// ---------------- helpers ----------------
__device__ __forceinline__ uint32_t f2tf32(float x) {
    uint32_t r;
    asm("cvt.rna.tf32.f32 %0, %1;" : "=r"(r) : "f"(x));
    return r;
}

__device__ __forceinline__ void mma_tf32(float c[4], const uint32_t a[4], const uint32_t b[2]) {
    asm volatile(
        "mma.sync.aligned.m16n8k8.row.col.f32.tf32.tf32.f32 "
        "{%0,%1,%2,%3}, {%4,%5,%6,%7}, {%8,%9}, {%0,%1,%2,%3};\n"
        : "+f"(c[0]), "+f"(c[1]), "+f"(c[2]), "+f"(c[3])
        : "r"(a[0]), "r"(a[1]), "r"(a[2]), "r"(a[3]), "r"(b[0]), "r"(b[1]));
}

// ---------------- fused GEMM + activation ----------------
// C[M, 1024] = x[M,512] @ [Wg;Wc]^T, then sigmoid/tanh (+bias) into g_gate/c_cand.
__global__ __launch_bounds__(256, 1) void gemm_act_kernel(
    const float* __restrict__ x,
    const float* __restrict__ Wg, const float* __restrict__ bg,
    const float* __restrict__ Wc, const float* __restrict__ bc)
{
    __shared__ float As[BM][BKP];
    __shared__ float Bs[BN][BKP];

    const int m0 = blockIdx.y * BM;
    const int n0 = blockIdx.x * BN;          // 0..1023 in steps of 128
    const bool isGate = (n0 < Ddim);
    const float* W = isGate ? Wg : Wc;
    const int nW0 = isGate ? n0 : (n0 - Ddim);

    const int tid  = threadIdx.x;
    const int warp = tid >> 5;
    const int lane = tid & 31;
    const int wm = warp >> 1;                // 0..3 -> 32 rows each
    const int wn = warp & 1;                 // 0..1 -> 64 cols each
    const int g  = lane >> 2;                // groupID
    const int tg = lane & 3;                 // threadID_in_group

    float acc[2][8][4];
    #pragma unroll
    for (int mt = 0; mt < 2; ++mt)
        #pragma unroll
        for (int nt = 0; nt < 8; ++nt)
            #pragma unroll
            for (int i = 0; i < 4; ++i) acc[mt][nt][i] = 0.0f;

    for (int kt = 0; kt < Kdim / BK; ++kt) {
        const int k0 = kt * BK;
        // load A tile 128x32 and B tile 128x32 (convert to tf32 once here)
        #pragma unroll
        for (int r = 0; r < 4; ++r) {
            int i   = tid + r * 256;          // 0..1023 float4 slots
            int row = i >> 3;
            int c4  = (i & 7) * 4;
            float4 va = *reinterpret_cast<const float4*>(&x[(size_t)(m0 + row) * Kdim + k0 + c4]);
            As[row][c4 + 0] = __uint_as_float(f2tf32(va.x));
            As[row][c4 + 1] = __uint_as_float(f2tf32(va.y));
            As[row][c4 + 2] = __uint_as_float(f2tf32(va.z));
            As[row][c4 + 3] = __uint_as_float(f2tf32(va.w));
            float4 vb = *reinterpret_cast<const float4*>(&W[(size_t)(nW0 + row) * Kdim + k0 + c4]);
            Bs[row][c4 + 0] = __uint_as_float(f2tf32(vb.x));
            Bs[row][c4 + 1] = __uint_as_float(f2tf32(vb.y));
            Bs[row][c4 + 2] = __uint_as_float(f2tf32(vb.z));
            Bs[row][c4 + 3] = __uint_as_float(f2tf32(vb.w));
        }
        __syncthreads();

        #pragma unroll
        for (int ks = 0; ks < BK / 8; ++ks) {
            const int k = ks * 8;
            uint32_t af[2][4], bf[8][2];
            #pragma unroll
            for (int mt = 0; mt < 2; ++mt) {
                int r = wm * 32 + mt * 16;
                af[mt][0] = __float_as_uint(As[r + g    ][k + tg    ]);
                af[mt][1] = __float_as_uint(As[r + g + 8][k + tg    ]);
                af[mt][2] = __float_as_uint(As[r + g    ][k + tg + 4]);
                af[mt][3] = __float_as_uint(As[r + g + 8][k + tg + 4]);
            }
            #pragma unroll
            for (int nt = 0; nt < 8; ++nt) {
                int n = wn * 64 + nt * 8 + g;
                bf[nt][0] = __float_as_uint(Bs[n][k + tg    ]);
                bf[nt][1] = __float_as_uint(Bs[n][k + tg + 4]);
            }
            #pragma unroll
            for (int mt = 0; mt < 2; ++mt)
                #pragma unroll
                for (int nt = 0; nt < 8; ++nt)
                    mma_tf32(acc[mt][nt], af[mt], bf[nt]);
        }
        __syncthreads();
    }

    // epilogue: bias + activation, write float2 (cols 2*tg, 2*tg+1 adjacent)
    #pragma unroll
    for (int mt = 0; mt < 2; ++mt) {
        #pragma unroll
        for (int nt = 0; nt < 8; ++nt) {
            int row0 = m0 + wm * 32 + mt * 16 + g;
            int col  = n0 + wn * 64 + nt * 8 + 2 * tg;   // global col in [0,1024)
            if (isGate) {
                float b0v = bg[col], b1v = bg[col + 1];
                float2 o0, o1;
                o0.x = 1.0f / (1.0f + expf(-(acc[mt][nt][0] + b0v)));
                o0.y = 1.0f / (1.0f + expf(-(acc[mt][nt][1] + b1v)));
                o1.x = 1.0f / (1.0f + expf(-(acc[mt][nt][2] + b0v)));
                o1.y = 1.0f / (1.0f + expf(-(acc[mt][nt][3] + b1v)));
                *reinterpret_cast<float2*>(&g_gate[(size_t)row0 * Ddim + col]) = o0;
                *reinterpret_cast<float2*>(&g_gate[(size_t)(row0 + 8) * Ddim + col]) = o1;
            } else {
                int cc = col - Ddim;
                float b0v = bc[cc], b1v = bc[cc + 1];
                float2 o0, o1;
                o0.x = tanhf(acc[mt][nt][0] + b0v);
                o0.y = tanhf(acc[mt][nt][1] + b1v);
                o1.x = tanhf(acc[mt][nt][2] + b0v);
                o1.y = tanhf(acc[mt][nt][3] + b1v);
                *reinterpret_cast<float2*>(&c_cand[(size_t)row0 * Ddim + cc]) = o0;
                *reinterpret_cast<float2*>(&c_cand[(size_t)(row0 + 8) * Ddim + cc]) = o1;
            }
        }
    }
}

// ---------------- scan phase 1: per-chunk composed (A, B) ----------------
// grid: B*NCHUNK blocks of D threads. h_end = A*h_start + Bv over the chunk.
__global__ __launch_bounds__(Ddim) void scan_phase1(void)
{
    const int b = blockIdx.x / NCHUNK;
    const int j = blockIdx.x % NCHUNK;
    const int d = threadIdx.x;
    const size_t base = ((size_t)b * Ldim + (size_t)j * CHUNK) * Ddim + d;
    const float* gp = g_gate + base;
    const float* cp = c_cand + base;

    float A = 1.0f, Bv = 0.0f;
    #pragma unroll 4
    for (int t = 0; t < CHUNK; ++t) {
        float gv = gp[(size_t)t * Ddim];
        float cv = cp[(size_t)t * Ddim];
        float a = 1.0f - gv;
        Bv = fmaf(a, Bv, gv * cv);
        A  = a * A;
    }
    chunkAB[((size_t)b * Ddim + d) * NCHUNK + j] = make_float2(A, Bv);
}

// ---------------- scan phase 2: scan chunk summaries (warp per channel) ----
__global__ __launch_bounds__(256) void scan_phase2(void)
{
    const int warp = threadIdx.x >> 5;
    const int lane = threadIdx.x & 31;
    const int ch = blockIdx.x * 8 + warp;    // NCHAN/8 = 256 blocks
    float2 v = chunkAB[(size_t)ch * NCHUNK + lane];   // (a, b) for chunk=lane
    #pragma unroll
    for (int off = 1; off < 32; off <<= 1) {
        float ap = __shfl_up_sync(0xffffffffu, v.x, off);
        float bp = __shfl_up_sync(0xffffffffu, v.y, off);
        if (lane >= off) {
            v.y = fmaf(v.x, bp, v.y);   // b = a_r*b_l + b_r
            v.x = v.x * ap;             // a = a_r*a_l
        }
    }
    // exclusive: h before chunk j = inclusive b of chunk j-1 (h0 = 0)
    float hprev = __shfl_up_sync(0xffffffffu, v.y, 1);
    chunkH[(size_t)ch * NCHUNK + lane] = (lane == 0) ? 0.0f : hprev;
}

// ---------------- scan phase 3: apply prefix, emit h ----------------
__global__ __launch_bounds__(Ddim) void scan_phase3(float* __restrict__ out)
{
    const int b = blockIdx.x / NCHUNK;
    const int j = blockIdx.x % NCHUNK;
    const int d = threadIdx.x;
    const size_t base = ((size_t)b * Ldim + (size_t)j * CHUNK) * Ddim + d;
    const float* gp = g_gate + base;
    const float* cp = c_cand + base;
    float* op = out + base;

    float h = chunkH[((size_t)b * Ddim + d) * NCHUNK + j];
    #pragma unroll 4
    for (int t = 0; t < CHUNK; ++t) {
        float gv = gp[(size_t)t * Ddim];
        float cv = cp[(size_t)t * Ddim];
        h = fmaf(gv, cv - h, h);        // (1-g)h + g c
        op[(size_t)t * Ddim] = h;
    }
}

// ---------------- launch ----------------
extern "C" void kernel_launch(void* const* d_in, const int* in_sizes, int n_in,
                              void* d_out, int out_size)
{
    const float* x  = (const float*)d_in[0];
    const float* Wg = (const float*)d_in[1];
    const float* bg = (const float*)d_in[2];
    const float* Wc = (const float*)d_in[3];
    const float* bc = (const float*)d_in[4];
    float* out = (float*)d_out;

    dim3 gemm_grid(Ntot / BN, Mdim / BM);   // (8, 256)
    gemm_act_kernel<<<gemm_grid, 256>>>(x, Wg, bg, Wc, bc);
    scan_phase1<<<Bdim * NCHUNK, Ddim>>>();
    scan_phase2<<<NCHAN / 8, 256>>>();
    scan_phase3<<<Bdim * NCHUNK, Ddim>>>(out);
}

// round 4
// speedup vs baseline: 1.3310x; 1.3310x over previous
#include <cuda_runtime.h>
#include <cuda_bf16.h>
#include <cstdint>
#include <math.h>

// Problem constants
#define Bdim 4
#define Ldim 8192
#define Ddim 512
#define Mdim (Bdim * Ldim)   // 32768
#define Ntot (2 * Ddim)      // 1024
#define Kdim 512

// GEMM tiling
#define BM 128
#define BN 128
#define BK 32
#define TILE_FLOATS (BM * BK)            // 4096 floats per tile
#define STAGE_FLOATS (2 * TILE_FLOATS)   // A + B
#define SMEM_BYTES (2 * STAGE_FLOATS * 4) // 65536 (2 stages)

// Scan config
#define CHUNK 128
#define NCHUNK (Ldim / CHUNK)        // 64
#define NCHAN (Bdim * Ddim)          // 2048

// ---------------- scratch ----------------
__device__ float g_gate[(size_t)Mdim * Ddim];
__device__ float c_cand[(size_t)Mdim * Ddim];
__device__ float2 chunkAB[NCHAN * NCHUNK];
__device__ float  chunkH[NCHAN * NCHUNK];

// ---------------- helpers ----------------
__device__ __forceinline__ uint32_t f2tf32(float x) {
    uint32_t r;
    asm("cvt.rna.tf32.f32 %0, %1;" : "=r"(r) : "f"(x));
    return r;
}

__device__ __forceinline__ void mma_tf32(float c[4], const uint32_t a[4], const uint32_t b[2]) {
    asm volatile(
        "mma.sync.aligned.m16n8k8.row.col.f32.tf32.tf32.f32 "
        "{%0,%1,%2,%3}, {%4,%5,%6,%7}, {%8,%9}, {%0,%1,%2,%3};\n"
        : "+f"(c[0]), "+f"(c[1]), "+f"(c[2]), "+f"(c[3])
        : "r"(a[0]), "r"(a[1]), "r"(a[2]), "r"(a[3]), "r"(b[0]), "r"(b[1]));
}

// XOR-swizzled smem index (row stride 32 floats, conflict-free for
// float4 STS and the mma fragment LDS pattern)
__device__ __forceinline__ int swz(int row, int col) {
    return (row << 5) + ((((col >> 2) ^ (row & 7)) << 2) | (col & 3));
}

__device__ __forceinline__ void store_tile(float* As, float* Bs,
                                           const float4* aR, const float4* bR,
                                           const int* lrow, const int* lj) {
    #pragma unroll
    for (int r = 0; r < 4; ++r) {
        int off = (lrow[r] << 5) + (((lj[r] ^ (lrow[r] & 7))) << 2);
        float4 a = aR[r], b = bR[r];
        float4 at, bt;
        at.x = __uint_as_float(f2tf32(a.x)); at.y = __uint_as_float(f2tf32(a.y));
        at.z = __uint_as_float(f2tf32(a.z)); at.w = __uint_as_float(f2tf32(a.w));
        bt.x = __uint_as_float(f2tf32(b.x)); bt.y = __uint_as_float(f2tf32(b.y));
        bt.z = __uint_as_float(f2tf32(b.z)); bt.w = __uint_as_float(f2tf32(b.w));
        *reinterpret_cast<float4*>(As + off) = at;
        *reinterpret_cast<float4*>(Bs + off) = bt;
    }
}

__device__ __forceinline__ void compute_tile(const float* As, const float* Bs,
                                             int wm, int wn, int g, int tg,
                                             float acc[2][8][4]) {
    #pragma unroll
    for (int ks = 0; ks < BK / 8; ++ks) {
        const int k = ks * 8;
        uint32_t af[2][4], bf[8][2];
        #pragma unroll
        for (int mt = 0; mt < 2; ++mt) {
            int r = wm * 32 + mt * 16;
            af[mt][0] = __float_as_uint(As[swz(r + g,     k + tg)]);
            af[mt][1] = __float_as_uint(As[swz(r + g + 8, k + tg)]);
            af[mt][2] = __float_as_uint(As[swz(r + g,     k + tg + 4)]);
            af[mt][3] = __float_as_uint(As[swz(r + g + 8, k + tg + 4)]);
        }
        #pragma unroll
        for (int nt = 0; nt < 8; ++nt) {
            int n = wn * 64 + nt * 8 + g;
            bf[nt][0] = __float_as_uint(Bs[swz(n, k + tg)]);
            bf[nt][1] = __float_as_uint(Bs[swz(n, k + tg + 4)]);
        }
        #pragma unroll
        for (int mt = 0; mt < 2; ++mt)
            #pragma unroll
            for (int nt = 0; nt < 8; ++nt)
                mma_tf32(acc[mt][nt], af[mt], bf[nt]);
    }
}

// ---------------- fused GEMM + activation (double-buffered) ----------------
__global__ __launch_bounds__(256, 1) void gemm_act_kernel(
    const float* __restrict__ x,
    const float* __restrict__ Wg, const float* __restrict__ bg,
    const float* __restrict__ Wc, const float* __restrict__ bc)
{
    extern __shared__ float sm[];

    const int m0 = blockIdx.y * BM;
    const int n0 = blockIdx.x * BN;
    const bool isGate = (n0 < Ddim);
    const float* W = isGate ? Wg : Wc;
    const int nW0 = isGate ? n0 : (n0 - Ddim);

    const int tid  = threadIdx.x;
    const int warp = tid >> 5;
    const int lane = tid & 31;
    const int wm = warp >> 1;
    const int wn = warp & 1;
    const int g  = lane >> 2;
    const int tg = lane & 3;

    int lrow[4], lj[4];
    #pragma unroll
    for (int r = 0; r < 4; ++r) { int i = tid + (r << 8); lrow[r] = i >> 3; lj[r] = i & 7; }

    float acc[2][8][4];
    #pragma unroll
    for (int mt = 0; mt < 2; ++mt)
        #pragma unroll
        for (int nt = 0; nt < 8; ++nt)
            #pragma unroll
            for (int i = 0; i < 4; ++i) acc[mt][nt][i] = 0.0f;

    float4 aR[4], bR[4];
    // prologue: tile kt=0
    #pragma unroll
    for (int r = 0; r < 4; ++r) {
        aR[r] = *reinterpret_cast<const float4*>(&x[(size_t)(m0 + lrow[r]) * Kdim + lj[r] * 4]);
        bR[r] = *reinterpret_cast<const float4*>(&W[(size_t)(nW0 + lrow[r]) * Kdim + lj[r] * 4]);
    }
    store_tile(sm, sm + TILE_FLOATS, aR, bR, lrow, lj);
    __syncthreads();

    const int NKT = Kdim / BK;  // 16
    for (int kt = 0; kt < NKT; ++kt) {
        const float* As = sm + (kt & 1) * STAGE_FLOATS;
        const float* Bs = As + TILE_FLOATS;
        const int ktn = kt + 1;
        if (ktn < NKT) {
            const int k0 = ktn * BK;
            #pragma unroll
            for (int r = 0; r < 4; ++r) {
                aR[r] = *reinterpret_cast<const float4*>(&x[(size_t)(m0 + lrow[r]) * Kdim + k0 + lj[r] * 4]);
                bR[r] = *reinterpret_cast<const float4*>(&W[(size_t)(nW0 + lrow[r]) * Kdim + k0 + lj[r] * 4]);
            }
        }
        compute_tile(As, Bs, wm, wn, g, tg, acc);
        if (ktn < NKT) {
            float* Asn = sm + (ktn & 1) * STAGE_FLOATS;
            store_tile(Asn, Asn + TILE_FLOATS, aR, bR, lrow, lj);
        }
        __syncthreads();
    }

    // epilogue: bias + activation
    #pragma unroll
    for (int mt = 0; mt < 2; ++mt) {
        #pragma unroll
        for (int nt = 0; nt < 8; ++nt) {
            int row0 = m0 + wm * 32 + mt * 16 + g;
            int col  = n0 + wn * 64 + nt * 8 + 2 * tg;
            if (isGate) {
                float b0v = bg[col], b1v = bg[col + 1];
                float2 o0, o1;
                o0.x = 1.0f / (1.0f + expf(-(acc[mt][nt][0] + b0v)));
                o0.y = 1.0f / (1.0f + expf(-(acc[mt][nt][1] + b1v)));
                o1.x = 1.0f / (1.0f + expf(-(acc[mt][nt][2] + b0v)));
                o1.y = 1.0f / (1.0f + expf(-(acc[mt][nt][3] + b1v)));
                *reinterpret_cast<float2*>(&g_gate[(size_t)row0 * Ddim + col]) = o0;
                *reinterpret_cast<float2*>(&g_gate[(size_t)(row0 + 8) * Ddim + col]) = o1;
            } else {
                int cc = col - Ddim;
                float b0v = bc[cc], b1v = bc[cc + 1];
                float2 o0, o1;
                o0.x = tanhf(acc[mt][nt][0] + b0v);
                o0.y = tanhf(acc[mt][nt][1] + b1v);
                o1.x = tanhf(acc[mt][nt][2] + b0v);
                o1.y = tanhf(acc[mt][nt][3] + b1v);
                *reinterpret_cast<float2*>(&c_cand[(size_t)row0 * Ddim + cc]) = o0;
                *reinterpret_cast<float2*>(&c_cand[(size_t)(row0 + 8) * Ddim + cc]) = o1;
            }
        }
    }
}

// ---------------- scan phase 1: per-chunk composed (A, B) ----------------
__global__ __launch_bounds__(Ddim) void scan_phase1(void)
{
    const int b = blockIdx.x >> 6;       // / NCHUNK
    const int j = blockIdx.x & (NCHUNK - 1);
    const int d = threadIdx.x;
    const size_t base = ((size_t)b * Ldim + (size_t)j * CHUNK) * Ddim + d;
    const float* gp = g_gate + base;
    const float* cp = c_cand + base;

    float A = 1.0f, Bv = 0.0f;
    #pragma unroll 4
    for (int t = 0; t < CHUNK; ++t) {
        float gv = gp[(size_t)t * Ddim];
        float cv = cp[(size_t)t * Ddim];
        float a = 1.0f - gv;
        Bv = fmaf(a, Bv, gv * cv);
        A  = a * A;
    }
    chunkAB[((size_t)b * Ddim + d) * NCHUNK + j] = make_float2(A, Bv);
}

// ---------------- scan phase 2: warp per channel, 64 chunks (2/lane) ------
__global__ __launch_bounds__(256) void scan_phase2(void)
{
    const int warp = threadIdx.x >> 5;
    const int lane = threadIdx.x & 31;
    const int ch = blockIdx.x * 8 + warp;

    float2 v0 = chunkAB[(size_t)ch * NCHUNK + 2 * lane];
    float2 v1 = chunkAB[(size_t)ch * NCHUNK + 2 * lane + 1];
    // compose pair (apply v0 then v1)
    float2 p;
    p.x = v1.x * v0.x;
    p.y = fmaf(v1.x, v0.y, v1.y);

    // inclusive warp scan over pairs
    #pragma unroll
    for (int off = 1; off < 32; off <<= 1) {
        float ap = __shfl_up_sync(0xffffffffu, p.x, off);
        float bp = __shfl_up_sync(0xffffffffu, p.y, off);
        if (lane >= off) {
            p.y = fmaf(p.x, bp, p.y);
            p.x = p.x * ap;
        }
    }
    // exclusive pair prefix applied to h0=0: h before pair = eB
    float eB = __shfl_up_sync(0xffffffffu, p.y, 1);
    if (lane == 0) eB = 0.0f;

    chunkH[(size_t)ch * NCHUNK + 2 * lane]     = eB;
    chunkH[(size_t)ch * NCHUNK + 2 * lane + 1] = fmaf(v0.x, eB, v0.y);
}

// ---------------- scan phase 3: apply prefix, emit h ----------------
__global__ __launch_bounds__(Ddim) void scan_phase3(float* __restrict__ out)
{
    const int b = blockIdx.x >> 6;
    const int j = blockIdx.x & (NCHUNK - 1);
    const int d = threadIdx.x;
    const size_t base = ((size_t)b * Ldim + (size_t)j * CHUNK) * Ddim + d;
    const float* gp = g_gate + base;
    const float* cp = c_cand + base;
    float* op = out + base;

    float h = chunkH[((size_t)b * Ddim + d) * NCHUNK + j];
    #pragma unroll 4
    for (int t = 0; t < CHUNK; ++t) {
        float gv = gp[(size_t)t * Ddim];
        float cv = cp[(size_t)t * Ddim];
        h = fmaf(gv, cv - h, h);
        op[(size_t)t * Ddim] = h;
    }
}

// ---------------- launch ----------------
extern "C" void kernel_launch(void* const* d_in, const int* in_sizes, int n_in,
                              void* d_out, int out_size)
{
    const float* x  = (const float*)d_in[0];
    const float* Wg = (const float*)d_in[1];
    const float* bg = (const float*)d_in[2];
    const float* Wc = (const float*)d_in[3];
    const float* bc = (const float*)d_in[4];
    float* out = (float*)d_out;

    cudaFuncSetAttribute(gemm_act_kernel,
                         cudaFuncAttributeMaxDynamicSharedMemorySize, SMEM_BYTES);

    dim3 gemm_grid(Ntot / BN, Mdim / BM);   // (8, 256)
    gemm_act_kernel<<<gemm_grid, 256, SMEM_BYTES>>>(x, Wg, bg, Wc, bc);
    scan_phase1<<<Bdim * NCHUNK, Ddim>>>();      // 256 blocks x 512
    scan_phase2<<<NCHAN / 8, 256>>>();
    scan_phase3<<<Bdim * NCHUNK, Ddim>>>(out);   // 256 blocks x 512
}

// round 6
// speedup vs baseline: 1.4138x; 1.0622x over previous
#include <cuda_runtime.h>
#include <cuda_bf16.h>
#include <cstdint>
#include <math.h>

// Problem constants
#define Bdim 4
#define Ldim 8192
#define Ddim 512
#define Mdim (Bdim * Ldim)   // 32768
#define Ntot (2 * Ddim)      // 1024
#define Kdim 512

// GEMM tiling (mma.sync tf32, cp.async 3-stage)
#define BM 256
#define BN 128
#define BK 32
#define NKT (Kdim / BK)                  // 16
#define A_FLOATS (BM * BK)               // 8192
#define B_FLOATS (BN * BK)               // 4096
#define STAGE_FLOATS (A_FLOATS + B_FLOATS)     // 12288
#define NSTAGES 3
#define SMEM_BYTES (NSTAGES * STAGE_FLOATS * 4) // 147456

// Scan config
#define CHUNK 64
#define NCHUNK (Ldim / CHUNK)        // 128
#define NCHAN (Bdim * Ddim)          // 2048

// ---------------- scratch ----------------
__device__ float g_gate[(size_t)Mdim * Ddim];
__device__ float c_cand[(size_t)Mdim * Ddim];
__device__ float W_rna[(size_t)Ntot * Kdim];    // [Wg;Wc] rounded to tf32 (rna)
__device__ float2 chunkAB[(size_t)NCHAN * NCHUNK];
__device__ float  chunkH[(size_t)NCHAN * NCHUNK];

// ---------------- helpers ----------------
__device__ __forceinline__ uint32_t smem_u32(const void* p) {
    uint32_t a;
    asm("{ .reg .u64 t; cvta.to.shared.u64 t, %1; cvt.u32.u64 %0, t; }" : "=r"(a) : "l"(p));
    return a;
}
__device__ __forceinline__ uint32_t f2tf32(float x) {
    uint32_t r;
    asm("cvt.rna.tf32.f32 %0, %1;" : "=r"(r) : "f"(x));
    return r;
}
__device__ __forceinline__ void cp16(uint32_t dst, const void* src) {
    asm volatile("cp.async.cg.shared.global [%0], [%1], 16;" :: "r"(dst), "l"(src));
}
__device__ __forceinline__ void cp_commit() { asm volatile("cp.async.commit_group;" ::: "memory"); }
template <int N>
__device__ __forceinline__ void cp_wait() { asm volatile("cp.async.wait_group %0;" :: "n"(N) : "memory"); }

__device__ __forceinline__ void mma_tf32(float c[4], const uint32_t a[4], const uint32_t b[2]) {
    asm volatile(
        "mma.sync.aligned.m16n8k8.row.col.f32.tf32.tf32.f32 "
        "{%0,%1,%2,%3}, {%4,%5,%6,%7}, {%8,%9}, {%0,%1,%2,%3};\n"
        : "+f"(c[0]), "+f"(c[1]), "+f"(c[2]), "+f"(c[3])
        : "r"(a[0]), "r"(a[1]), "r"(a[2]), "r"(a[3]), "r"(b[0]), "r"(b[1]));
}

// XOR-swizzled smem float index (row stride 32 floats / 128B; conflict-free
// for both 16B cp.async stores and the mma fragment LDS pattern)
__device__ __forceinline__ int swz(int row, int col) {
    return (row << 5) + ((((col >> 2) ^ (row & 7)) << 2) | (col & 3));
}

// ---------------- pre-round W to tf32 (rna) ----------------
__global__ void preround_kernel(const float* __restrict__ Wg, const float* __restrict__ Wc)
{
    int i = blockIdx.x * 256 + threadIdx.x;       // 0..131071 float4 slots
    const int half = (Ntot / 2) * Kdim / 4;       // 65536
    const float4* src = (i < half) ? (const float4*)Wg : (const float4*)Wc;
    int j = (i < half) ? i : i - half;
    float4 v = src[j];
    v.x = __uint_as_float(f2tf32(v.x));
    v.y = __uint_as_float(f2tf32(v.y));
    v.z = __uint_as_float(f2tf32(v.z));
    v.w = __uint_as_float(f2tf32(v.w));
    reinterpret_cast<float4*>(W_rna)[i] = v;
}

// ---------------- fused GEMM + activation ----------------
__global__ __launch_bounds__(512, 1) void gemm_act_kernel(
    const float* __restrict__ x,
    const float* __restrict__ bg, const float* __restrict__ bc)
{
    extern __shared__ float sm[];
    const uint32_t smem_base = smem_u32(sm);

    const int m0 = blockIdx.y * BM;
    const int n0 = blockIdx.x * BN;
    const bool isGate = (n0 < Ddim);
    const float* W = W_rna + (size_t)n0 * Kdim;   // rows n0..n0+127 of [Wg;Wc]

    const int tid  = threadIdx.x;
    const int warp = tid >> 5;
    const int lane = tid & 31;
    const int wm = warp >> 2;                // 0..3 -> 64 rows each
    const int wn = warp & 3;                 // 0..3 -> 32 cols each
    const int g  = lane >> 2;
    const int tg = lane & 3;

    // cp.async stage loader: A 2048 float4 (4/thread), B 1024 float4 (2/thread)
    auto load_stage = [&](int kt) {
        const uint32_t base = smem_base + (kt % NSTAGES) * (STAGE_FLOATS * 4);
        const uint32_t bbase = base + A_FLOATS * 4;
        const int k0 = kt * BK;
        #pragma unroll
        for (int r = 0; r < 4; ++r) {
            int i = tid + (r << 9);
            int row = i >> 3, j = i & 7;
            cp16(base + 4 * ((row << 5) + ((j ^ (row & 7)) << 2)),
                 x + (size_t)(m0 + row) * Kdim + k0 + j * 4);
        }
        #pragma unroll
        for (int r = 0; r < 2; ++r) {
            int i = tid + (r << 9);
            int row = i >> 3, j = i & 7;
            cp16(bbase + 4 * ((row << 5) + ((j ^ (row & 7)) << 2)),
                 W + (size_t)row * Kdim + k0 + j * 4);
        }
        cp_commit();
    };

    float acc[4][4][4];
    #pragma unroll
    for (int mt = 0; mt < 4; ++mt)
        #pragma unroll
        for (int nt = 0; nt < 4; ++nt)
            #pragma unroll
            for (int i = 0; i < 4; ++i) acc[mt][nt][i] = 0.0f;

    load_stage(0);
    load_stage(1);

    for (int s = 0; s < NKT; ++s) {
        if (s < NKT - 2) cp_wait<1>(); else cp_wait<0>();
        __syncthreads();

        const float* As = sm + (s % NSTAGES) * STAGE_FLOATS;
        const float* Bs = As + A_FLOATS;
        #pragma unroll
        for (int ks = 0; ks < BK / 8; ++ks) {
            const int k = ks * 8;
            uint32_t af[4][4], bf[4][2];
            #pragma unroll
            for (int mt = 0; mt < 4; ++mt) {
                int r = wm * 64 + mt * 16;
                af[mt][0] = __float_as_uint(As[swz(r + g,     k + tg)]);
                af[mt][1] = __float_as_uint(As[swz(r + g + 8, k + tg)]);
                af[mt][2] = __float_as_uint(As[swz(r + g,     k + tg + 4)]);
                af[mt][3] = __float_as_uint(As[swz(r + g + 8, k + tg + 4)]);
            }
            #pragma unroll
            for (int nt = 0; nt < 4; ++nt) {
                int n = wn * 32 + nt * 8 + g;
                bf[nt][0] = __float_as_uint(Bs[swz(n, k + tg)]);
                bf[nt][1] = __float_as_uint(Bs[swz(n, k + tg + 4)]);
            }
            #pragma unroll
            for (int mt = 0; mt < 4; ++mt)
                #pragma unroll
                for (int nt = 0; nt < 4; ++nt)
                    mma_tf32(acc[mt][nt], af[mt], bf[nt]);
        }
        __syncthreads();

        if (s + 2 < NKT) load_stage(s + 2);
    }

    // epilogue: bias + activation
    float* dst = isGate ? g_gate : c_cand;
    const float* bias = isGate ? bg : bc;
    const int cb = n0 & (Ddim - 1);
    #pragma unroll
    for (int mt = 0; mt < 4; ++mt) {
        #pragma unroll
        for (int nt = 0; nt < 4; ++nt) {
            int row0 = m0 + wm * 64 + mt * 16 + g;
            int col  = cb + wn * 32 + nt * 8 + 2 * tg;
            float b0v = bias[col], b1v = bias[col + 1];
            float2 o0, o1;
            if (isGate) {
                o0.x = 1.0f / (1.0f + expf(-(acc[mt][nt][0] + b0v)));
                o0.y = 1.0f / (1.0f + expf(-(acc[mt][nt][1] + b1v)));
                o1.x = 1.0f / (1.0f + expf(-(acc[mt][nt][2] + b0v)));
                o1.y = 1.0f / (1.0f + expf(-(acc[mt][nt][3] + b1v)));
            } else {
                o0.x = tanhf(acc[mt][nt][0] + b0v);
                o0.y = tanhf(acc[mt][nt][1] + b1v);
                o1.x = tanhf(acc[mt][nt][2] + b0v);
                o1.y = tanhf(acc[mt][nt][3] + b1v);
            }
            *reinterpret_cast<float2*>(&dst[(size_t)row0 * Ddim + col]) = o0;
            *reinterpret_cast<float2*>(&dst[(size_t)(row0 + 8) * Ddim + col]) = o1;
        }
    }
}

// ---------------- scan phase 1: per-chunk composed (A, B) ----------------
__global__ __launch_bounds__(Ddim) void scan_phase1(void)
{
    const int b = blockIdx.x >> 7;               // / NCHUNK
    const int j = blockIdx.x & (NCHUNK - 1);
    const int d = threadIdx.x;
    const size_t base = ((size_t)b * Ldim + (size_t)j * CHUNK) * Ddim + d;
    const float* gp = g_gate + base;
    const float* cp = c_cand + base;

    float A = 1.0f, Bv = 0.0f;
    #pragma unroll 4
    for (int t = 0; t < CHUNK; ++t) {
        float gv = gp[(size_t)t * Ddim];
        float cv = cp[(size_t)t * Ddim];
        float a = 1.0f - gv;
        Bv = fmaf(a, Bv, gv * cv);
        A  = a * A;
    }
    chunkAB[((size_t)b * Ddim + d) * NCHUNK + j] = make_float2(A, Bv);
}

// ---------------- scan phase 2: warp per channel, 128 chunks (4/lane) -----
__global__ __launch_bounds__(256) void scan_phase2(void)
{
    const int warp = threadIdx.x >> 5;
    const int lane = threadIdx.x & 31;
    const int ch = blockIdx.x * 8 + warp;
    const size_t base = (size_t)ch * NCHUNK + 4 * lane;

    float2 v0 = chunkAB[base + 0];
    float2 v1 = chunkAB[base + 1];
    float2 v2 = chunkAB[base + 2];
    float2 v3 = chunkAB[base + 3];
    float2 p01, p23, p;
    p01.x = v1.x * v0.x;  p01.y = fmaf(v1.x, v0.y, v1.y);
    p23.x = v3.x * v2.x;  p23.y = fmaf(v3.x, v2.y, v3.y);
    p.x = p23.x * p01.x;  p.y = fmaf(p23.x, p01.y, p23.y);

    #pragma unroll
    for (int off = 1; off < 32; off <<= 1) {
        float ap = __shfl_up_sync(0xffffffffu, p.x, off);
        float bp = __shfl_up_sync(0xffffffffu, p.y, off);
        if (lane >= off) {
            p.y = fmaf(p.x, bp, p.y);
            p.x = p.x * ap;
        }
    }
    float h = __shfl_up_sync(0xffffffffu, p.y, 1);
    if (lane == 0) h = 0.0f;

    chunkH[base + 0] = h;
    h = fmaf(v0.x, h, v0.y);
    chunkH[base + 1] = h;
    h = fmaf(v1.x, h, v1.y);
    chunkH[base + 2] = h;
    h = fmaf(v2.x, h, v2.y);
    chunkH[base + 3] = h;
}

// ---------------- scan phase 3: apply prefix, emit h ----------------
__global__ __launch_bounds__(Ddim) void scan_phase3(float* __restrict__ out)
{
    const int b = blockIdx.x >> 7;
    const int j = blockIdx.x & (NCHUNK - 1);
    const int d = threadIdx.x;
    const size_t base = ((size_t)b * Ldim + (size_t)j * CHUNK) * Ddim + d;
    const float* gp = g_gate + base;
    const float* cp = c_cand + base;
    float* op = out + base;

    float h = chunkH[((size_t)b * Ddim + d) * NCHUNK + j];
    #pragma unroll 4
    for (int t = 0; t < CHUNK; ++t) {
        float gv = gp[(size_t)t * Ddim];
        float cv = cp[(size_t)t * Ddim];
        h = fmaf(gv, cv - h, h);
        op[(size_t)t * Ddim] = h;
    }
}

// ---------------- launch ----------------
extern "C" void kernel_launch(void* const* d_in, const int* in_sizes, int n_in,
                              void* d_out, int out_size)
{
    const float* x  = (const float*)d_in[0];
    const float* Wg = (const float*)d_in[1];
    const float* bg = (const float*)d_in[2];
    const float* Wc = (const float*)d_in[3];
    const float* bc = (const float*)d_in[4];
    float* out = (float*)d_out;

    cudaFuncSetAttribute(gemm_act_kernel,
                         cudaFuncAttributeMaxDynamicSharedMemorySize, SMEM_BYTES);

    preround_kernel<<<512, 256>>>(Wg, Wc);
    dim3 gemm_grid(Ntot / BN, Mdim / BM);           // (8, 128) = 1024 CTAs
    gemm_act_kernel<<<gemm_grid, 512, SMEM_BYTES>>>(x, bg, bc);
    scan_phase1<<<Bdim * NCHUNK, Ddim>>>();         // 512 blocks
    scan_phase2<<<NCHAN / 8, 256>>>();
    scan_phase3<<<Bdim * NCHUNK, Ddim>>>(out);      // 512 blocks
}